// round 15
// baseline (speedup 1.0000x reference)
#include <cuda_runtime.h>
#include <cuda_fp16.h>
#include <stdint.h>
#include <math.h>

#define Nn    4096
#define INF   512
#define OUTF  128
#define CN    16384
#define TOTD  67108864.0
#define SCALE 2.5f
#define KC    64
#define NCHUNK 64
#define RCH   256          // colsum row-chunks (64 rows each)

__device__ __forceinline__ uint32_t smem_to_u32(const void* p) {
    uint32_t a;
    asm("{ .reg .u64 t; cvta.to.shared.u64 t, %1; cvt.u32.u64 %0, t; }" : "=r"(a) : "l"(p));
    return a;
}
__device__ __forceinline__ uint32_t packh2(float lo, float hi) {
    uint32_t r;
    asm("cvt.rn.f16x2.f32 %0, %1, %2;" : "=r"(r) : "f"(hi), "f"(lo));
    return r;
}
#define LDSM4(r, a)                                                                   \
    asm volatile("ldmatrix.sync.aligned.m8n8.x4.shared.b16 {%0,%1,%2,%3}, [%4];"      \
        : "=r"((r)[0]), "=r"((r)[1]), "=r"((r)[2]), "=r"((r)[3]) : "r"(a))
#define MMAH(d, a, b0, b1)                                                            \
    asm volatile("mma.sync.aligned.m16n8k16.row.col.f32.f16.f16.f32 "                 \
        "{%0,%1,%2,%3},{%4,%5,%6,%7},{%8,%9},{%0,%1,%2,%3};"                          \
        : "+f"((d)[0]), "+f"((d)[1]), "+f"((d)[2]), "+f"((d)[3])                      \
        : "r"((a)[0]), "r"((a)[1]), "r"((a)[2]), "r"((a)[3]), "r"(b0), "r"(b1))
#define CPASYNC16(dst, src)                                                           \
    asm volatile("cp.async.cg.shared.global [%0], [%1], 16;" :: "r"(dst), "l"(src))
#define CPCOMMIT() asm volatile("cp.async.commit_group;" ::: "memory")
#define CPWAIT1()  asm volatile("cp.async.wait_group 1;" ::: "memory")
#define CPWAITALL() asm volatile("cp.async.wait_group 0;" ::: "memory")

__device__ __forceinline__ uint32_t swz(uint32_t off) { return off ^ ((off >> 3) & 0x70); }

// ---------------- scratch ----------------
__device__ float  g_h[Nn * OUTF];
__device__ float  g_Wt[INF * OUTF];
__device__ double g_part[1024];
__device__ float  g_colpart[RCH * Nn];            // 4MB
__device__ int    g_mstride;
__device__ unsigned short g_Bf[OUTF * Nn];        // [f][k] fp16 of g[k][f]*1024
__device__ unsigned short g_Af[(size_t)CN * Nn];  // [r][k] fp16 of masked exp
__device__ float  g_Pk[2 * 2097152];              // split-K partials (2 x 8MB)

// ---------------- launch 0: W transpose + mask dtype detect ----------------
__global__ void k_init(const float* __restrict__ W, const unsigned char* __restrict__ mask) {
    int o = blockIdx.x * 256 + threadIdx.x;   // 65536 total
    int f = o & (OUTF - 1);
    int k = o >> 7;
    g_Wt[o] = W[f * INF + k];
    if (blockIdx.x == 0) {
        __shared__ int s[256];
        int nz = 0;
        for (int i = threadIdx.x; i < 65536; i += 256)
            if ((i & 3) != 0 && mask[i]) nz++;
        s[threadIdx.x] = nz;
        __syncthreads();
        for (int oo = 128; oo > 0; oo >>= 1) {
            if (threadIdx.x < oo) s[threadIdx.x] += s[threadIdx.x + oo];
            __syncthreads();
        }
        if (threadIdx.x == 0) g_mstride = (s[0] == 0) ? 4 : 1;
    }
}

// ---------------- launch 1: mean partials ----------------
__global__ void k_meanpart(const float4* __restrict__ att4) {
    float acc = 0.f;
    int stride = gridDim.x * blockDim.x;
    int n4 = (CN * Nn) / 4;
#pragma unroll 4
    for (int i = blockIdx.x * blockDim.x + threadIdx.x; i < n4; i += stride) {
        float4 v = att4[i];
        acc += (v.x + v.y) + (v.z + v.w);
    }
    __shared__ double s[256];
    s[threadIdx.x] = (double)acc;
    __syncthreads();
    for (int o = 128; o > 0; o >>= 1) {
        if (threadIdx.x < o) s[threadIdx.x] += s[threadIdx.x + o];
        __syncthreads();
    }
    if (threadIdx.x == 0) g_part[blockIdx.x] = s[0];
}

// ---------------- launch 2: GEMM1 h = x @ Wt ----------------
__global__ __launch_bounds__(256) void k_gemm1(const float* __restrict__ x) {
    __shared__ __align__(16) float As[16][32];
    __shared__ __align__(16) float Bs[16][128];
    int tid = threadIdx.x;
    int r0 = blockIdx.x * 32;
    int tr = tid >> 4;
    int tc = tid & 15;
    float acc[2][8];
#pragma unroll
    for (int i = 0; i < 2; i++)
#pragma unroll
        for (int j = 0; j < 8; j++) acc[i][j] = 0.f;

    for (int k0 = 0; k0 < INF; k0 += 16) {
        if (tid < 128) {
            int row = tid >> 2, c4 = tid & 3;
            float4 v = *(const float4*)(x + (size_t)(r0 + row) * INF + k0 + c4 * 4);
            As[c4 * 4 + 0][row] = v.x;
            As[c4 * 4 + 1][row] = v.y;
            As[c4 * 4 + 2][row] = v.z;
            As[c4 * 4 + 3][row] = v.w;
        }
#pragma unroll
        for (int q = 0; q < 2; q++) {
            int g = tid + q * 256;
            int kk = g >> 5, f4 = g & 31;
            *(float4*)&Bs[kk][f4 * 4] = *(const float4*)(g_Wt + (k0 + kk) * OUTF + f4 * 4);
        }
        __syncthreads();
#pragma unroll
        for (int kk = 0; kk < 16; kk++) {
            float a0 = As[kk][tr * 2], a1 = As[kk][tr * 2 + 1];
            float b[8];
            *(float4*)(b)     = *(const float4*)&Bs[kk][tc * 8];
            *(float4*)(b + 4) = *(const float4*)&Bs[kk][tc * 8 + 4];
#pragma unroll
            for (int j = 0; j < 8; j++) {
                acc[0][j] += a0 * b[j];
                acc[1][j] += a1 * b[j];
            }
        }
        __syncthreads();
    }
#pragma unroll
    for (int i = 0; i < 2; i++) {
        float* op = g_h + (size_t)(r0 + tr * 2 + i) * OUTF + tc * 8;
        *(float4*)op       = make_float4(acc[i][0], acc[i][1], acc[i][2], acc[i][3]);
        *(float4*)(op + 4) = make_float4(acc[i][4], acc[i][5], acc[i][6], acc[i][7]);
    }
}

// ---------------- launch 3: mean finalize + column sums + Af materialize ----------
// grid (4, 256): 64 rows per block -> 1024 CTAs, high occupancy & MLP.
__global__ void k_colsum(const float4* __restrict__ att4,
                         const unsigned char* __restrict__ mask) {
    __shared__ double sd[256];
    __shared__ float smean;
    int t = threadIdx.x;
    {
        double a = g_part[t] + g_part[t + 256] + g_part[t + 512] + g_part[t + 768];
        sd[t] = a;
        __syncthreads();
        for (int o = 128; o > 0; o >>= 1) {
            if (t < o) sd[t] += sd[t + o];
            __syncthreads();
        }
        if (t == 0) smean = (float)(sd[0] / TOTD);
        __syncthreads();
    }
    float mean = smean;
    int mstride = g_mstride;
    int col4 = blockIdx.x * 256 + t;              // 0..1023
    int r0 = blockIdx.y * 64;
    const float4* p = att4 + (size_t)r0 * 1024 + col4;
    float ax = 0.f, ay = 0.f, az = 0.f, aw = 0.f;
#pragma unroll 4
    for (int i = 0; i < 64; i++) {
        size_t eidx = ((size_t)(r0 + i)) * Nn + col4 * 4;
        float4 v = p[(size_t)i * 1024];
        float e0 = (v.x > mean) ? __expf(v.x) : 0.f;
        float e1 = (v.y > mean) ? __expf(v.y) : 0.f;
        float e2 = (v.z > mean) ? __expf(v.z) : 0.f;
        float e3 = (v.w > mean) ? __expf(v.w) : 0.f;
        ax += e0; ay += e1; az += e2; aw += e3;
        uint32_t mk;
        if (mstride == 1) {
            mk = *(const uint32_t*)(mask + eidx);
        } else {
            int4 mi = *(const int4*)((const int*)mask + eidx);
            mk = (mi.x ? 1u : 0u) | (mi.y ? 0x100u : 0u) |
                 (mi.z ? 0x10000u : 0u) | (mi.w ? 0x1000000u : 0u);
        }
        float a0 = (mk & 0xFFu)       ? e0 : 0.f;
        float a1 = (mk & 0xFF00u)     ? e1 : 0.f;
        float a2 = (mk & 0xFF0000u)   ? e2 : 0.f;
        float a3 = (mk & 0xFF000000u) ? e3 : 0.f;
        *(uint2*)(g_Af + eidx) = make_uint2(packh2(a0, a1), packh2(a2, a3));
    }
    float* cp = g_colpart + (size_t)blockIdx.y * Nn + col4 * 4;
    *(float4*)cp = make_float4(ax, ay, az, aw);
}

// ---------------- launch 4: rs (inline, 256 chunks) + B prep ----------------
__global__ void k_bprep() {
    __shared__ float tile[32][33];
    __shared__ float rss[32];
    int k0 = blockIdx.x * 32, f0 = blockIdx.y * 32;
    int t = threadIdx.x;
    {
        int ki = t >> 3, f4 = (t & 7) * 4;
        float4 v = *(const float4*)(g_h + (size_t)(k0 + ki) * OUTF + f0 + f4);
        tile[ki][f4 + 0] = v.x; tile[ki][f4 + 1] = v.y;
        tile[ki][f4 + 2] = v.z; tile[ki][f4 + 3] = v.w;
    }
    // 256 threads x 32 columns: thread t sums chunks [seg*32, +32) for col k0+(t>>3)
    {
        __shared__ float psum[32][9];
        int col = t >> 3, seg = t & 7;     // 8 segs x 32 chunks
        float s = 0.f;
#pragma unroll 8
        for (int ch = seg * 32; ch < seg * 32 + 32; ch++)
            s += g_colpart[(size_t)ch * Nn + k0 + col];
        psum[col][seg] = s;
        __syncthreads();
        if (t < 32) {
            float ss = 0.f;
#pragma unroll
            for (int q = 0; q < 8; q++) ss += psum[t][q];
            rss[t] = 1024.f * SCALE / ss;
        }
    }
    __syncthreads();
    int fi = t >> 3, k4 = (t & 7) * 4;
    uint32_t p01 = packh2(tile[k4 + 0][fi] * rss[k4 + 0], tile[k4 + 1][fi] * rss[k4 + 1]);
    uint32_t p23 = packh2(tile[k4 + 2][fi] * rss[k4 + 2], tile[k4 + 3][fi] * rss[k4 + 3]);
    size_t o = (size_t)(f0 + fi) * Nn + k0 + k4;
    *(uint2*)(g_Bf + o) = make_uint2(p01, p23);
}

// ---------------- launch 5: split-K fp16 GEMM, 3-stage cp.async ----------------
__global__ __launch_bounds__(256, 2) void k_gemm2m() {
    extern __shared__ __align__(128) char sm[];
    uint32_t smb = smem_to_u32(sm);
    const int tid = threadIdx.x, lane = tid & 31, w = tid >> 5;
    const int r0 = blockIdx.x * 128;
    const int c0 = blockIdx.y * (NCHUNK / 2);
    const int wm0 = (w & 3) * 32;
    const int wn0 = (w >> 2) * 64;

    float acc[2][8][4];
#pragma unroll
    for (int mt = 0; mt < 2; mt++)
#pragma unroll
        for (int nt = 0; nt < 8; nt++)
#pragma unroll
            for (int q = 0; q < 4; q++) acc[mt][nt][q] = 0.f;

    const int li = lane >> 3;
    const uint32_t aRow = wm0 + (li & 1) * 8 + (lane & 7);
    const uint32_t aKof = (li >> 1) * 16;
    const uint32_t bRow = wn0 + ((lane >> 4) & 1) * 8 + (lane & 7);
    const uint32_t bKof = ((lane >> 3) & 1) * 16;
    const int cprow = tid >> 3, cpseg = tid & 7;

#define CPST(c_, st_)                                                                 \
    {                                                                                 \
        uint32_t sbase = smb + (uint32_t)(st_) * 32768u;                              \
        _Pragma("unroll")                                                             \
        for (int j = 0; j < 4; j++) {                                                 \
            int row = cprow + j * 32;                                                 \
            uint32_t sw = swz((uint32_t)(row * 128 + cpseg * 16));                    \
            CPASYNC16(sbase + sw,                                                     \
                      g_Af + (size_t)(r0 + row) * Nn + (c_) * KC + cpseg * 8);        \
        }                                                                             \
        _Pragma("unroll")                                                             \
        for (int j = 0; j < 4; j++) {                                                 \
            int f = cprow + j * 32;                                                   \
            uint32_t sw = swz((uint32_t)(f * 128 + cpseg * 16));                      \
            CPASYNC16(sbase + 16384u + sw,                                            \
                      g_Bf + (size_t)f * Nn + (c_) * KC + cpseg * 8);                 \
        }                                                                             \
        CPCOMMIT();                                                                   \
    }

    CPST(c0, 0);
    CPST(c0 + 1, 1);

    const int NC2 = NCHUNK / 2;
    for (int c = 0; c < NC2; c++) {
        if (c < NC2 - 2) { CPWAIT1(); } else { CPWAITALL(); }
        __syncthreads();
        if (c + 2 < NC2) {
            int st2 = c + 2; st2 -= (st2 / 3) * 3;
            CPST(c0 + c + 2, st2);
        }
        int st = c - (c / 3) * 3;
        uint32_t abase = smb + (uint32_t)st * 32768u;
        uint32_t bbase = abase + 16384u;
#pragma unroll
        for (int ks = 0; ks < 4; ks++) {
            uint32_t ah[2][4];
#pragma unroll
            for (int mt = 0; mt < 2; mt++) {
                uint32_t sw = swz((aRow + mt * 16) * 128 + ks * 32 + aKof);
                LDSM4(ah[mt], abase + sw);
            }
#pragma unroll
            for (int nt2 = 0; nt2 < 4; nt2++) {
                uint32_t sw = swz((bRow + nt2 * 16) * 128 + ks * 32 + bKof);
                uint32_t bh[4];
                LDSM4(bh, bbase + sw);
#pragma unroll
                for (int mt = 0; mt < 2; mt++) {
                    MMAH(acc[mt][nt2 * 2],     ah[mt], bh[0], bh[1]);
                    MMAH(acc[mt][nt2 * 2 + 1], ah[mt], bh[2], bh[3]);
                }
            }
        }
    }

    float* P = g_Pk + ((size_t)blockIdx.y << 21);
    const int orow = lane >> 2, ocol = (lane & 3) * 2;
#pragma unroll
    for (int mt = 0; mt < 2; mt++) {
#pragma unroll
        for (int nt = 0; nt < 8; nt++) {
            int f = wn0 + nt * 8 + ocol;
            int r1 = r0 + wm0 + mt * 16 + orow;
            *(float2*)(P + (size_t)r1 * OUTF + f) = make_float2(acc[mt][nt][0], acc[mt][nt][1]);
            *(float2*)(P + (size_t)(r1 + 8) * OUTF + f) = make_float2(acc[mt][nt][2], acc[mt][nt][3]);
        }
    }
#undef CPST
}

// ---------------- launch 6: reduce partials + permute + unscale ----------------
__global__ void k_red(float* __restrict__ out) {
    const float dsc = 1.f / 1024.f;
    int idx = blockIdx.x * 256 + threadIdx.x;     // 524288
    int r = idx >> 5, f4 = (idx & 31) * 4;
    float4 a = *(const float4*)(g_Pk + (size_t)r * OUTF + f4);
    float4 b = *(const float4*)(g_Pk + 2097152 + (size_t)r * OUTF + f4);
    int n = r & (Nn - 1), c = r >> 12;
    *(float4*)(out + (size_t)n * 512 + c * OUTF + f4) =
        make_float4((a.x + b.x) * dsc, (a.y + b.y) * dsc,
                    (a.z + b.z) * dsc, (a.w + b.w) * dsc);
}

// ---------------- launch ----------------
extern "C" void kernel_launch(void* const* d_in, const int* in_sizes, int n_in,
                              void* d_out, int out_size) {
    const float* x = (const float*)d_in[0];
    const float* att = (const float*)d_in[1];
    const float* W = (const float*)d_in[2];
    const unsigned char* mask = (const unsigned char*)d_in[3];
    float* out = (float*)d_out;

    static const int SMEM2 = 98304;   // 3 stages x 32KB
    cudaFuncSetAttribute(k_gemm2m, cudaFuncAttributeMaxDynamicSharedMemorySize, SMEM2);

    k_init<<<256, 256>>>(W, mask);                       // 0
    k_meanpart<<<1024, 256>>>((const float4*)att);       // 1
    k_gemm1<<<128, 256>>>(x);                            // 2
    k_colsum<<<dim3(4, 256), 256>>>((const float4*)att, mask);  // 3
    k_bprep<<<dim3(128, 4), 256>>>();                    // 4
    k_gemm2m<<<dim3(128, 2), 256, SMEM2>>>();            // 5  <- ncu -s 5 captures this
    k_red<<<2048, 256>>>(out);                           // 6
}

// round 16
// speedup vs baseline: 1.2986x; 1.2986x over previous
#include <cuda_runtime.h>
#include <cuda_fp16.h>
#include <stdint.h>
#include <math.h>

#define Nn    4096
#define INF   512
#define OUTF  128
#define CN    16384
#define TOTD  67108864.0
#define SCALE 2.5f
#define KC    64
#define NCHUNK 64
#define RCH   512          // colsum row-chunks (32 rows each)

__device__ __forceinline__ uint32_t smem_to_u32(const void* p) {
    uint32_t a;
    asm("{ .reg .u64 t; cvta.to.shared.u64 t, %1; cvt.u32.u64 %0, t; }" : "=r"(a) : "l"(p));
    return a;
}
__device__ __forceinline__ uint32_t packh2(float lo, float hi) {
    uint32_t r;
    asm("cvt.rn.f16x2.f32 %0, %1, %2;" : "=r"(r) : "f"(hi), "f"(lo));
    return r;
}
#define LDSM4(r, a)                                                                   \
    asm volatile("ldmatrix.sync.aligned.m8n8.x4.shared.b16 {%0,%1,%2,%3}, [%4];"      \
        : "=r"((r)[0]), "=r"((r)[1]), "=r"((r)[2]), "=r"((r)[3]) : "r"(a))
#define MMAH(d, a, b0, b1)                                                            \
    asm volatile("mma.sync.aligned.m16n8k16.row.col.f32.f16.f16.f32 "                 \
        "{%0,%1,%2,%3},{%4,%5,%6,%7},{%8,%9},{%0,%1,%2,%3};"                          \
        : "+f"((d)[0]), "+f"((d)[1]), "+f"((d)[2]), "+f"((d)[3])                      \
        : "r"((a)[0]), "r"((a)[1]), "r"((a)[2]), "r"((a)[3]), "r"(b0), "r"(b1))
#define CPASYNC16(dst, src)                                                           \
    asm volatile("cp.async.cg.shared.global [%0], [%1], 16;" :: "r"(dst), "l"(src))
#define CPCOMMIT() asm volatile("cp.async.commit_group;" ::: "memory")
#define CPWAIT1()  asm volatile("cp.async.wait_group 1;" ::: "memory")
#define CPWAITALL() asm volatile("cp.async.wait_group 0;" ::: "memory")

__device__ __forceinline__ uint32_t swz(uint32_t off) { return off ^ ((off >> 3) & 0x70); }

// ---------------- scratch ----------------
__device__ float  g_h[Nn * OUTF];
__device__ float  g_Wt[INF * OUTF];
__device__ double g_part[1024];
__device__ float  g_colpart[RCH * Nn];            // 8MB
__device__ int    g_mstride;
__device__ unsigned short g_Bf[OUTF * Nn];        // [f][k] fp16 of g[k][f]*1024
__device__ unsigned short g_Af[(size_t)CN * Nn];  // [r][k] fp16 of masked exp
__device__ float  g_Pk[2 * 2097152];              // split-K partials (2 x 8MB)

// ---------------- launch 0: W transpose + mask dtype detect ----------------
__global__ void k_init(const float* __restrict__ W, const unsigned char* __restrict__ mask) {
    int o = blockIdx.x * 256 + threadIdx.x;   // 65536 total
    int f = o & (OUTF - 1);
    int k = o >> 7;
    g_Wt[o] = W[f * INF + k];
    if (blockIdx.x == 0) {
        __shared__ int s[256];
        int nz = 0;
        for (int i = threadIdx.x; i < 65536; i += 256)
            if ((i & 3) != 0 && mask[i]) nz++;
        s[threadIdx.x] = nz;
        __syncthreads();
        for (int oo = 128; oo > 0; oo >>= 1) {
            if (threadIdx.x < oo) s[threadIdx.x] += s[threadIdx.x + oo];
            __syncthreads();
        }
        if (threadIdx.x == 0) g_mstride = (s[0] == 0) ? 4 : 1;
    }
}

// ---------------- launch 1: mean partials ----------------
__global__ void k_meanpart(const float4* __restrict__ att4) {
    float acc = 0.f;
    int stride = gridDim.x * blockDim.x;
    int n4 = (CN * Nn) / 4;
#pragma unroll 4
    for (int i = blockIdx.x * blockDim.x + threadIdx.x; i < n4; i += stride) {
        float4 v = att4[i];
        acc += (v.x + v.y) + (v.z + v.w);
    }
    __shared__ double s[256];
    s[threadIdx.x] = (double)acc;
    __syncthreads();
    for (int o = 128; o > 0; o >>= 1) {
        if (threadIdx.x < o) s[threadIdx.x] += s[threadIdx.x + o];
        __syncthreads();
    }
    if (threadIdx.x == 0) g_part[blockIdx.x] = s[0];
}

// ---------------- launch 2: GEMM1 h = x @ Wt ----------------
__global__ __launch_bounds__(256) void k_gemm1(const float* __restrict__ x) {
    __shared__ __align__(16) float As[16][32];
    __shared__ __align__(16) float Bs[16][128];
    int tid = threadIdx.x;
    int r0 = blockIdx.x * 32;
    int tr = tid >> 4;
    int tc = tid & 15;
    float acc[2][8];
#pragma unroll
    for (int i = 0; i < 2; i++)
#pragma unroll
        for (int j = 0; j < 8; j++) acc[i][j] = 0.f;

    for (int k0 = 0; k0 < INF; k0 += 16) {
        if (tid < 128) {
            int row = tid >> 2, c4 = tid & 3;
            float4 v = *(const float4*)(x + (size_t)(r0 + row) * INF + k0 + c4 * 4);
            As[c4 * 4 + 0][row] = v.x;
            As[c4 * 4 + 1][row] = v.y;
            As[c4 * 4 + 2][row] = v.z;
            As[c4 * 4 + 3][row] = v.w;
        }
#pragma unroll
        for (int q = 0; q < 2; q++) {
            int g = tid + q * 256;
            int kk = g >> 5, f4 = g & 31;
            *(float4*)&Bs[kk][f4 * 4] = *(const float4*)(g_Wt + (k0 + kk) * OUTF + f4 * 4);
        }
        __syncthreads();
#pragma unroll
        for (int kk = 0; kk < 16; kk++) {
            float a0 = As[kk][tr * 2], a1 = As[kk][tr * 2 + 1];
            float b[8];
            *(float4*)(b)     = *(const float4*)&Bs[kk][tc * 8];
            *(float4*)(b + 4) = *(const float4*)&Bs[kk][tc * 8 + 4];
#pragma unroll
            for (int j = 0; j < 8; j++) {
                acc[0][j] += a0 * b[j];
                acc[1][j] += a1 * b[j];
            }
        }
        __syncthreads();
    }
#pragma unroll
    for (int i = 0; i < 2; i++) {
        float* op = g_h + (size_t)(r0 + tr * 2 + i) * OUTF + tc * 8;
        *(float4*)op       = make_float4(acc[i][0], acc[i][1], acc[i][2], acc[i][3]);
        *(float4*)(op + 4) = make_float4(acc[i][4], acc[i][5], acc[i][6], acc[i][7]);
    }
}

// ---------------- launch 3: mean finalize + column sums + Af materialize ----------
// grid (2, 512): thread covers 8 consecutive k; 32 rows per block.
// Per row-iter: 2x LDG.128 (att) + 1x LDG.64 (mask u8) + 1x STG.128 (Af).
__global__ void k_colsum(const float* __restrict__ att,
                         const unsigned char* __restrict__ mask) {
    __shared__ double sd[256];
    __shared__ float smean;
    int t = threadIdx.x;
    {
        double a = g_part[t] + g_part[t + 256] + g_part[t + 512] + g_part[t + 768];
        sd[t] = a;
        __syncthreads();
        for (int o = 128; o > 0; o >>= 1) {
            if (t < o) sd[t] += sd[t + o];
            __syncthreads();
        }
        if (t == 0) smean = (float)(sd[0] / TOTD);
        __syncthreads();
    }
    const float mean = smean;
    const int mstride = g_mstride;
    const int col8 = blockIdx.x * 256 + t;        // 0..511
    const int r0 = blockIdx.y * 32;
    size_t base = (size_t)r0 * Nn + (size_t)col8 * 8;
    const char* pa = (const char*)(att + base);
    const char* pm = (mstride == 1) ? (const char*)(mask + base)
                                    : (const char*)((const int*)mask + base);
    char* pf = (char*)(g_Af + base);

    float s0 = 0.f, s1 = 0.f, s2 = 0.f, s3 = 0.f;
    float s4 = 0.f, s5 = 0.f, s6 = 0.f, s7 = 0.f;
#pragma unroll 2
    for (int i = 0; i < 32; i++) {
        float4 v0 = *(const float4*)(pa);
        float4 v1 = *(const float4*)(pa + 16);
        float e0 = (v0.x > mean) ? __expf(v0.x) : 0.f;
        float e1 = (v0.y > mean) ? __expf(v0.y) : 0.f;
        float e2 = (v0.z > mean) ? __expf(v0.z) : 0.f;
        float e3 = (v0.w > mean) ? __expf(v0.w) : 0.f;
        float e4 = (v1.x > mean) ? __expf(v1.x) : 0.f;
        float e5 = (v1.y > mean) ? __expf(v1.y) : 0.f;
        float e6 = (v1.z > mean) ? __expf(v1.z) : 0.f;
        float e7 = (v1.w > mean) ? __expf(v1.w) : 0.f;
        s0 += e0; s1 += e1; s2 += e2; s3 += e3;
        s4 += e4; s5 += e5; s6 += e6; s7 += e7;
        uint32_t mk0, mk1;
        if (mstride == 1) {
            uint2 mm = *(const uint2*)(pm);
            mk0 = mm.x; mk1 = mm.y;
        } else {
            int4 ma = *(const int4*)(pm);
            int4 mb = *(const int4*)(pm + 16);
            mk0 = (ma.x ? 1u : 0u) | (ma.y ? 0x100u : 0u) |
                  (ma.z ? 0x10000u : 0u) | (ma.w ? 0x1000000u : 0u);
            mk1 = (mb.x ? 1u : 0u) | (mb.y ? 0x100u : 0u) |
                  (mb.z ? 0x10000u : 0u) | (mb.w ? 0x1000000u : 0u);
        }
        float a0 = (mk0 & 0xFFu)       ? e0 : 0.f;
        float a1 = (mk0 & 0xFF00u)     ? e1 : 0.f;
        float a2 = (mk0 & 0xFF0000u)   ? e2 : 0.f;
        float a3 = (mk0 & 0xFF000000u) ? e3 : 0.f;
        float a4 = (mk1 & 0xFFu)       ? e4 : 0.f;
        float a5 = (mk1 & 0xFF00u)     ? e5 : 0.f;
        float a6 = (mk1 & 0xFF0000u)   ? e6 : 0.f;
        float a7 = (mk1 & 0xFF000000u) ? e7 : 0.f;
        *(uint4*)(pf) = make_uint4(packh2(a0, a1), packh2(a2, a3),
                                   packh2(a4, a5), packh2(a6, a7));
        pa += Nn * 4;
        pm += (mstride == 1) ? Nn : Nn * 4;
        pf += Nn * 2;
    }
    float* cp = g_colpart + (size_t)blockIdx.y * Nn + (size_t)col8 * 8;
    *(float4*)cp       = make_float4(s0, s1, s2, s3);
    *(float4*)(cp + 4) = make_float4(s4, s5, s6, s7);
}

// ---------------- launch 4: rs (inline, 512 chunks) + B prep ----------------
__global__ void k_bprep() {
    __shared__ float tile[32][33];
    __shared__ float rss[32];
    int k0 = blockIdx.x * 32, f0 = blockIdx.y * 32;
    int t = threadIdx.x;
    {
        int ki = t >> 3, f4 = (t & 7) * 4;
        float4 v = *(const float4*)(g_h + (size_t)(k0 + ki) * OUTF + f0 + f4);
        tile[ki][f4 + 0] = v.x; tile[ki][f4 + 1] = v.y;
        tile[ki][f4 + 2] = v.z; tile[ki][f4 + 3] = v.w;
    }
    // 256 threads, 32 columns: thread t sums chunks [seg*64, +64) for col k0+(t>>3)
    {
        __shared__ float psum[32][9];
        int col = t >> 3, seg = t & 7;     // 8 segs x 64 chunks
        float s = 0.f;
#pragma unroll 8
        for (int ch = seg * 64; ch < seg * 64 + 64; ch++)
            s += g_colpart[(size_t)ch * Nn + k0 + col];
        psum[col][seg] = s;
        __syncthreads();
        if (t < 32) {
            float ss = 0.f;
#pragma unroll
            for (int q = 0; q < 8; q++) ss += psum[t][q];
            rss[t] = 1024.f * SCALE / ss;
        }
    }
    __syncthreads();
    int fi = t >> 3, k4 = (t & 7) * 4;
    uint32_t p01 = packh2(tile[k4 + 0][fi] * rss[k4 + 0], tile[k4 + 1][fi] * rss[k4 + 1]);
    uint32_t p23 = packh2(tile[k4 + 2][fi] * rss[k4 + 2], tile[k4 + 3][fi] * rss[k4 + 3]);
    size_t o = (size_t)(f0 + fi) * Nn + k0 + k4;
    *(uint2*)(g_Bf + o) = make_uint2(p01, p23);
}

// ---------------- launch 5: split-K fp16 GEMM, 3-stage cp.async ----------------
__global__ __launch_bounds__(256, 2) void k_gemm2m() {
    extern __shared__ __align__(128) char sm[];
    uint32_t smb = smem_to_u32(sm);
    const int tid = threadIdx.x, lane = tid & 31, w = tid >> 5;
    const int r0 = blockIdx.x * 128;
    const int c0 = blockIdx.y * (NCHUNK / 2);
    const int wm0 = (w & 3) * 32;
    const int wn0 = (w >> 2) * 64;

    float acc[2][8][4];
#pragma unroll
    for (int mt = 0; mt < 2; mt++)
#pragma unroll
        for (int nt = 0; nt < 8; nt++)
#pragma unroll
            for (int q = 0; q < 4; q++) acc[mt][nt][q] = 0.f;

    const int li = lane >> 3;
    const uint32_t aRow = wm0 + (li & 1) * 8 + (lane & 7);
    const uint32_t aKof = (li >> 1) * 16;
    const uint32_t bRow = wn0 + ((lane >> 4) & 1) * 8 + (lane & 7);
    const uint32_t bKof = ((lane >> 3) & 1) * 16;
    const int cprow = tid >> 3, cpseg = tid & 7;

#define CPST(c_, st_)                                                                 \
    {                                                                                 \
        uint32_t sbase = smb + (uint32_t)(st_) * 32768u;                              \
        _Pragma("unroll")                                                             \
        for (int j = 0; j < 4; j++) {                                                 \
            int row = cprow + j * 32;                                                 \
            uint32_t sw = swz((uint32_t)(row * 128 + cpseg * 16));                    \
            CPASYNC16(sbase + sw,                                                     \
                      g_Af + (size_t)(r0 + row) * Nn + (c_) * KC + cpseg * 8);        \
        }                                                                             \
        _Pragma("unroll")                                                             \
        for (int j = 0; j < 4; j++) {                                                 \
            int f = cprow + j * 32;                                                   \
            uint32_t sw = swz((uint32_t)(f * 128 + cpseg * 16));                      \
            CPASYNC16(sbase + 16384u + sw,                                            \
                      g_Bf + (size_t)f * Nn + (c_) * KC + cpseg * 8);                 \
        }                                                                             \
        CPCOMMIT();                                                                   \
    }

    CPST(c0, 0);
    CPST(c0 + 1, 1);

    const int NC2 = NCHUNK / 2;
    for (int c = 0; c < NC2; c++) {
        if (c < NC2 - 2) { CPWAIT1(); } else { CPWAITALL(); }
        __syncthreads();
        if (c + 2 < NC2) {
            int st2 = c + 2; st2 -= (st2 / 3) * 3;
            CPST(c0 + c + 2, st2);
        }
        int st = c - (c / 3) * 3;
        uint32_t abase = smb + (uint32_t)st * 32768u;
        uint32_t bbase = abase + 16384u;
#pragma unroll
        for (int ks = 0; ks < 4; ks++) {
            uint32_t ah[2][4];
#pragma unroll
            for (int mt = 0; mt < 2; mt++) {
                uint32_t sw = swz((aRow + mt * 16) * 128 + ks * 32 + aKof);
                LDSM4(ah[mt], abase + sw);
            }
#pragma unroll
            for (int nt2 = 0; nt2 < 4; nt2++) {
                uint32_t sw = swz((bRow + nt2 * 16) * 128 + ks * 32 + bKof);
                uint32_t bh[4];
                LDSM4(bh, bbase + sw);
#pragma unroll
                for (int mt = 0; mt < 2; mt++) {
                    MMAH(acc[mt][nt2 * 2],     ah[mt], bh[0], bh[1]);
                    MMAH(acc[mt][nt2 * 2 + 1], ah[mt], bh[2], bh[3]);
                }
            }
        }
    }

    float* P = g_Pk + ((size_t)blockIdx.y << 21);
    const int orow = lane >> 2, ocol = (lane & 3) * 2;
#pragma unroll
    for (int mt = 0; mt < 2; mt++) {
#pragma unroll
        for (int nt = 0; nt < 8; nt++) {
            int f = wn0 + nt * 8 + ocol;
            int r1 = r0 + wm0 + mt * 16 + orow;
            *(float2*)(P + (size_t)r1 * OUTF + f) = make_float2(acc[mt][nt][0], acc[mt][nt][1]);
            *(float2*)(P + (size_t)(r1 + 8) * OUTF + f) = make_float2(acc[mt][nt][2], acc[mt][nt][3]);
        }
    }
#undef CPST
}

// ---------------- launch 6: reduce partials + permute + unscale ----------------
__global__ void k_red(float* __restrict__ out) {
    const float dsc = 1.f / 1024.f;
    int idx = blockIdx.x * 256 + threadIdx.x;     // 524288
    int r = idx >> 5, f4 = (idx & 31) * 4;
    float4 a = *(const float4*)(g_Pk + (size_t)r * OUTF + f4);
    float4 b = *(const float4*)(g_Pk + 2097152 + (size_t)r * OUTF + f4);
    int n = r & (Nn - 1), c = r >> 12;
    *(float4*)(out + (size_t)n * 512 + c * OUTF + f4) =
        make_float4((a.x + b.x) * dsc, (a.y + b.y) * dsc,
                    (a.z + b.z) * dsc, (a.w + b.w) * dsc);
}

// ---------------- launch ----------------
extern "C" void kernel_launch(void* const* d_in, const int* in_sizes, int n_in,
                              void* d_out, int out_size) {
    const float* x = (const float*)d_in[0];
    const float* att = (const float*)d_in[1];
    const float* W = (const float*)d_in[2];
    const unsigned char* mask = (const unsigned char*)d_in[3];
    float* out = (float*)d_out;

    static const int SMEM2 = 98304;   // 3 stages x 32KB
    cudaFuncSetAttribute(k_gemm2m, cudaFuncAttributeMaxDynamicSharedMemorySize, SMEM2);

    k_init<<<256, 256>>>(W, mask);                       // 0
    k_meanpart<<<1024, 256>>>((const float4*)att);       // 1
    k_gemm1<<<128, 256>>>(x);                            // 2
    k_colsum<<<dim3(2, 512), 256>>>(att, mask);          // 3
    k_bprep<<<dim3(128, 4), 256>>>();                    // 4
    k_gemm2m<<<dim3(128, 2), 256, SMEM2>>>();            // 5  <- ncu -s 5 captures this
    k_red<<<2048, 256>>>(out);                           // 6
}

// round 17
// speedup vs baseline: 1.4975x; 1.1531x over previous
#include <cuda_runtime.h>
#include <cuda_fp16.h>
#include <stdint.h>
#include <math.h>

#define Nn    4096
#define INF   512
#define OUTF  128
#define CN    16384
#define TOTD  67108864.0
#define SCALE 2.5f
#define KC    64
#define NCHUNK 64
#define RCH   512          // colsum row-chunks (32 rows each)

__device__ __forceinline__ uint32_t smem_to_u32(const void* p) {
    uint32_t a;
    asm("{ .reg .u64 t; cvta.to.shared.u64 t, %1; cvt.u32.u64 %0, t; }" : "=r"(a) : "l"(p));
    return a;
}
__device__ __forceinline__ uint32_t packh2(float lo, float hi) {
    uint32_t r;
    asm("cvt.rn.f16x2.f32 %0, %1, %2;" : "=r"(r) : "f"(hi), "f"(lo));
    return r;
}
#define LDSM4(r, a)                                                                   \
    asm volatile("ldmatrix.sync.aligned.m8n8.x4.shared.b16 {%0,%1,%2,%3}, [%4];"      \
        : "=r"((r)[0]), "=r"((r)[1]), "=r"((r)[2]), "=r"((r)[3]) : "r"(a))
#define MMAH(d, a, b0, b1)                                                            \
    asm volatile("mma.sync.aligned.m16n8k16.row.col.f32.f16.f16.f32 "                 \
        "{%0,%1,%2,%3},{%4,%5,%6,%7},{%8,%9},{%0,%1,%2,%3};"                          \
        : "+f"((d)[0]), "+f"((d)[1]), "+f"((d)[2]), "+f"((d)[3])                      \
        : "r"((a)[0]), "r"((a)[1]), "r"((a)[2]), "r"((a)[3]), "r"(b0), "r"(b1))
#define CPASYNC16(dst, src)                                                           \
    asm volatile("cp.async.cg.shared.global [%0], [%1], 16;" :: "r"(dst), "l"(src))
#define CPCOMMIT() asm volatile("cp.async.commit_group;" ::: "memory")
#define CPWAIT1()  asm volatile("cp.async.wait_group 1;" ::: "memory")
#define CPWAITALL() asm volatile("cp.async.wait_group 0;" ::: "memory")

__device__ __forceinline__ uint32_t swz(uint32_t off) { return off ^ ((off >> 3) & 0x70); }

// ---------------- scratch ----------------
__device__ float  g_h[Nn * OUTF];
__device__ float  g_Wt[INF * OUTF];
__device__ double g_part[1024];
__device__ float  g_colpart[RCH * Nn];            // 8MB
__device__ int    g_mstride;
__device__ unsigned short g_Bf[OUTF * Nn];        // [f][k] fp16 of g[k][f]*1024
__device__ unsigned short g_Af[(size_t)CN * Nn];  // [r][k] fp16 of masked exp
__device__ float  g_Pk[2 * 2097152];              // split-K partials (2 x 8MB)

// ---------------- launch 0: mean partials + W transpose + mask detect ----------------
__global__ void k_meanpart(const float4* __restrict__ att4,
                           const float* __restrict__ W,
                           const unsigned char* __restrict__ mask) {
    // W transpose spread over first 256 blocks (256 elems each)
    if (blockIdx.x < 256) {
        int o = blockIdx.x * 256 + threadIdx.x;
        g_Wt[o] = W[(o & (OUTF - 1)) * INF + (o >> 7)];
    }
    // mask dtype detect in block 0
    if (blockIdx.x == 0) {
        __shared__ int s[256];
        int nz = 0;
        for (int i = threadIdx.x; i < 65536; i += 256)
            if ((i & 3) != 0 && mask[i]) nz++;
        s[threadIdx.x] = nz;
        __syncthreads();
        for (int oo = 128; oo > 0; oo >>= 1) {
            if (threadIdx.x < oo) s[threadIdx.x] += s[threadIdx.x + oo];
            __syncthreads();
        }
        if (threadIdx.x == 0) g_mstride = (s[0] == 0) ? 4 : 1;
        __syncthreads();
    }
    // mean partial
    float acc = 0.f;
    int stride = gridDim.x * blockDim.x;
    int n4 = (CN * Nn) / 4;
#pragma unroll 4
    for (int i = blockIdx.x * blockDim.x + threadIdx.x; i < n4; i += stride) {
        float4 v = att4[i];
        acc += (v.x + v.y) + (v.z + v.w);
    }
    __shared__ double sd[256];
    sd[threadIdx.x] = (double)acc;
    __syncthreads();
    for (int o = 128; o > 0; o >>= 1) {
        if (threadIdx.x < o) sd[threadIdx.x] += sd[threadIdx.x + o];
        __syncthreads();
    }
    if (threadIdx.x == 0) g_part[blockIdx.x] = sd[0];
}

// ---------------- launch 1: fused gemm1 (blocks 0-127) + colsum/Af (blocks 128-1151) --
__global__ __launch_bounds__(256) void k_fused1(const float* __restrict__ x,
                                                const float* __restrict__ att,
                                                const unsigned char* __restrict__ mask) {
    __shared__ __align__(16) char shm[10240];
    int t = threadIdx.x;

    if (blockIdx.x < 128) {
        // ---------------- GEMM1: h = x @ Wt (BM=32) ----------------
        float (*As)[32]  = (float(*)[32])shm;            // 2048 B
        float (*Bs)[128] = (float(*)[128])(shm + 2048);  // 8192 B
        int r0 = blockIdx.x * 32;
        int tr = t >> 4;
        int tc = t & 15;
        float acc[2][8];
#pragma unroll
        for (int i = 0; i < 2; i++)
#pragma unroll
            for (int j = 0; j < 8; j++) acc[i][j] = 0.f;

        for (int k0 = 0; k0 < INF; k0 += 16) {
            if (t < 128) {
                int row = t >> 2, c4 = t & 3;
                float4 v = *(const float4*)(x + (size_t)(r0 + row) * INF + k0 + c4 * 4);
                As[c4 * 4 + 0][row] = v.x;
                As[c4 * 4 + 1][row] = v.y;
                As[c4 * 4 + 2][row] = v.z;
                As[c4 * 4 + 3][row] = v.w;
            }
#pragma unroll
            for (int q = 0; q < 2; q++) {
                int g = t + q * 256;
                int kk = g >> 5, f4 = g & 31;
                *(float4*)&Bs[kk][f4 * 4] = *(const float4*)(g_Wt + (k0 + kk) * OUTF + f4 * 4);
            }
            __syncthreads();
#pragma unroll
            for (int kk = 0; kk < 16; kk++) {
                float a0 = As[kk][tr * 2], a1 = As[kk][tr * 2 + 1];
                float b[8];
                *(float4*)(b)     = *(const float4*)&Bs[kk][tc * 8];
                *(float4*)(b + 4) = *(const float4*)&Bs[kk][tc * 8 + 4];
#pragma unroll
                for (int j = 0; j < 8; j++) {
                    acc[0][j] += a0 * b[j];
                    acc[1][j] += a1 * b[j];
                }
            }
            __syncthreads();
        }
#pragma unroll
        for (int i = 0; i < 2; i++) {
            float* op = g_h + (size_t)(r0 + tr * 2 + i) * OUTF + tc * 8;
            *(float4*)op       = make_float4(acc[i][0], acc[i][1], acc[i][2], acc[i][3]);
            *(float4*)(op + 4) = make_float4(acc[i][4], acc[i][5], acc[i][6], acc[i][7]);
        }
    } else {
        // ---------------- colsum + Af materialize ----------------
        double* sd = (double*)shm;                 // 2048 B
        float* smeanp = (float*)(shm + 2048);
        {
            double a = g_part[t] + g_part[t + 256] + g_part[t + 512] + g_part[t + 768];
            sd[t] = a;
            __syncthreads();
            for (int o = 128; o > 0; o >>= 1) {
                if (t < o) sd[t] += sd[t + o];
                __syncthreads();
            }
            if (t == 0) *smeanp = (float)(sd[0] / TOTD);
            __syncthreads();
        }
        const float mean = *smeanp;
        const int mstride = g_mstride;
        int bb = blockIdx.x - 128;                 // 0..1023
        const int col8 = (bb & 1) * 256 + t;       // 0..511
        const int r0 = (bb >> 1) * 32;
        size_t base = (size_t)r0 * Nn + (size_t)col8 * 8;
        const char* pa = (const char*)(att + base);
        const char* pm = (mstride == 1) ? (const char*)(mask + base)
                                        : (const char*)((const int*)mask + base);
        char* pf = (char*)(g_Af + base);

        float s0 = 0.f, s1 = 0.f, s2 = 0.f, s3 = 0.f;
        float s4 = 0.f, s5 = 0.f, s6 = 0.f, s7 = 0.f;
#pragma unroll 2
        for (int i = 0; i < 32; i++) {
            float4 v0 = *(const float4*)(pa);
            float4 v1 = *(const float4*)(pa + 16);
            float e0 = (v0.x > mean) ? __expf(v0.x) : 0.f;
            float e1 = (v0.y > mean) ? __expf(v0.y) : 0.f;
            float e2 = (v0.z > mean) ? __expf(v0.z) : 0.f;
            float e3 = (v0.w > mean) ? __expf(v0.w) : 0.f;
            float e4 = (v1.x > mean) ? __expf(v1.x) : 0.f;
            float e5 = (v1.y > mean) ? __expf(v1.y) : 0.f;
            float e6 = (v1.z > mean) ? __expf(v1.z) : 0.f;
            float e7 = (v1.w > mean) ? __expf(v1.w) : 0.f;
            s0 += e0; s1 += e1; s2 += e2; s3 += e3;
            s4 += e4; s5 += e5; s6 += e6; s7 += e7;
            uint32_t mk0, mk1;
            if (mstride == 1) {
                uint2 mm = *(const uint2*)(pm);
                mk0 = mm.x; mk1 = mm.y;
            } else {
                int4 ma = *(const int4*)(pm);
                int4 mb = *(const int4*)(pm + 16);
                mk0 = (ma.x ? 1u : 0u) | (ma.y ? 0x100u : 0u) |
                      (ma.z ? 0x10000u : 0u) | (ma.w ? 0x1000000u : 0u);
                mk1 = (mb.x ? 1u : 0u) | (mb.y ? 0x100u : 0u) |
                      (mb.z ? 0x10000u : 0u) | (mb.w ? 0x1000000u : 0u);
            }
            float a0 = (mk0 & 0xFFu)       ? e0 : 0.f;
            float a1 = (mk0 & 0xFF00u)     ? e1 : 0.f;
            float a2 = (mk0 & 0xFF0000u)   ? e2 : 0.f;
            float a3 = (mk0 & 0xFF000000u) ? e3 : 0.f;
            float a4 = (mk1 & 0xFFu)       ? e4 : 0.f;
            float a5 = (mk1 & 0xFF00u)     ? e5 : 0.f;
            float a6 = (mk1 & 0xFF0000u)   ? e6 : 0.f;
            float a7 = (mk1 & 0xFF000000u) ? e7 : 0.f;
            *(uint4*)(pf) = make_uint4(packh2(a0, a1), packh2(a2, a3),
                                       packh2(a4, a5), packh2(a6, a7));
            pa += Nn * 4;
            pm += (mstride == 1) ? Nn : Nn * 4;
            pf += Nn * 2;
        }
        float* cp = g_colpart + (size_t)(bb >> 1) * Nn + (size_t)col8 * 8;
        *(float4*)cp       = make_float4(s0, s1, s2, s3);
        *(float4*)(cp + 4) = make_float4(s4, s5, s6, s7);
    }
}

// ---------------- launch 2: rs (inline, 512 chunks) + B prep ----------------
__global__ void k_bprep() {
    __shared__ float tile[32][33];
    __shared__ float rss[32];
    int k0 = blockIdx.x * 32, f0 = blockIdx.y * 32;
    int t = threadIdx.x;
    {
        int ki = t >> 3, f4 = (t & 7) * 4;
        float4 v = *(const float4*)(g_h + (size_t)(k0 + ki) * OUTF + f0 + f4);
        tile[ki][f4 + 0] = v.x; tile[ki][f4 + 1] = v.y;
        tile[ki][f4 + 2] = v.z; tile[ki][f4 + 3] = v.w;
    }
    {
        __shared__ float psum[32][9];
        int col = t >> 3, seg = t & 7;     // 8 segs x 64 chunks
        float s = 0.f;
#pragma unroll 8
        for (int ch = seg * 64; ch < seg * 64 + 64; ch++)
            s += g_colpart[(size_t)ch * Nn + k0 + col];
        psum[col][seg] = s;
        __syncthreads();
        if (t < 32) {
            float ss = 0.f;
#pragma unroll
            for (int q = 0; q < 8; q++) ss += psum[t][q];
            rss[t] = 1024.f * SCALE / ss;
        }
    }
    __syncthreads();
    int fi = t >> 3, k4 = (t & 7) * 4;
    uint32_t p01 = packh2(tile[k4 + 0][fi] * rss[k4 + 0], tile[k4 + 1][fi] * rss[k4 + 1]);
    uint32_t p23 = packh2(tile[k4 + 2][fi] * rss[k4 + 2], tile[k4 + 3][fi] * rss[k4 + 3]);
    size_t o = (size_t)(f0 + fi) * Nn + k0 + k4;
    *(uint2*)(g_Bf + o) = make_uint2(p01, p23);
}

// ---------------- launch 3: split-K fp16 GEMM, 3-stage cp.async ----------------
__global__ __launch_bounds__(256, 2) void k_gemm2m() {
    extern __shared__ __align__(128) char sm[];
    uint32_t smb = smem_to_u32(sm);
    const int tid = threadIdx.x, lane = tid & 31, w = tid >> 5;
    const int r0 = blockIdx.x * 128;
    const int c0 = blockIdx.y * (NCHUNK / 2);
    const int wm0 = (w & 3) * 32;
    const int wn0 = (w >> 2) * 64;

    float acc[2][8][4];
#pragma unroll
    for (int mt = 0; mt < 2; mt++)
#pragma unroll
        for (int nt = 0; nt < 8; nt++)
#pragma unroll
            for (int q = 0; q < 4; q++) acc[mt][nt][q] = 0.f;

    const int li = lane >> 3;
    const uint32_t aRow = wm0 + (li & 1) * 8 + (lane & 7);
    const uint32_t aKof = (li >> 1) * 16;
    const uint32_t bRow = wn0 + ((lane >> 4) & 1) * 8 + (lane & 7);
    const uint32_t bKof = ((lane >> 3) & 1) * 16;
    const int cprow = tid >> 3, cpseg = tid & 7;

#define CPST(c_, st_)                                                                 \
    {                                                                                 \
        uint32_t sbase = smb + (uint32_t)(st_) * 32768u;                              \
        _Pragma("unroll")                                                             \
        for (int j = 0; j < 4; j++) {                                                 \
            int row = cprow + j * 32;                                                 \
            uint32_t sw = swz((uint32_t)(row * 128 + cpseg * 16));                    \
            CPASYNC16(sbase + sw,                                                     \
                      g_Af + (size_t)(r0 + row) * Nn + (c_) * KC + cpseg * 8);        \
        }                                                                             \
        _Pragma("unroll")                                                             \
        for (int j = 0; j < 4; j++) {                                                 \
            int f = cprow + j * 32;                                                   \
            uint32_t sw = swz((uint32_t)(f * 128 + cpseg * 16));                      \
            CPASYNC16(sbase + 16384u + sw,                                            \
                      g_Bf + (size_t)f * Nn + (c_) * KC + cpseg * 8);                 \
        }                                                                             \
        CPCOMMIT();                                                                   \
    }

    CPST(c0, 0);
    CPST(c0 + 1, 1);

    const int NC2 = NCHUNK / 2;
    for (int c = 0; c < NC2; c++) {
        if (c < NC2 - 2) { CPWAIT1(); } else { CPWAITALL(); }
        __syncthreads();
        if (c + 2 < NC2) {
            int st2 = c + 2; st2 -= (st2 / 3) * 3;
            CPST(c0 + c + 2, st2);
        }
        int st = c - (c / 3) * 3;
        uint32_t abase = smb + (uint32_t)st * 32768u;
        uint32_t bbase = abase + 16384u;
#pragma unroll
        for (int ks = 0; ks < 4; ks++) {
            uint32_t ah[2][4];
#pragma unroll
            for (int mt = 0; mt < 2; mt++) {
                uint32_t sw = swz((aRow + mt * 16) * 128 + ks * 32 + aKof);
                LDSM4(ah[mt], abase + sw);
            }
#pragma unroll
            for (int nt2 = 0; nt2 < 4; nt2++) {
                uint32_t sw = swz((bRow + nt2 * 16) * 128 + ks * 32 + bKof);
                uint32_t bh[4];
                LDSM4(bh, bbase + sw);
#pragma unroll
                for (int mt = 0; mt < 2; mt++) {
                    MMAH(acc[mt][nt2 * 2],     ah[mt], bh[0], bh[1]);
                    MMAH(acc[mt][nt2 * 2 + 1], ah[mt], bh[2], bh[3]);
                }
            }
        }
    }

    float* P = g_Pk + ((size_t)blockIdx.y << 21);
    const int orow = lane >> 2, ocol = (lane & 3) * 2;
#pragma unroll
    for (int mt = 0; mt < 2; mt++) {
#pragma unroll
        for (int nt = 0; nt < 8; nt++) {
            int f = wn0 + nt * 8 + ocol;
            int r1 = r0 + wm0 + mt * 16 + orow;
            *(float2*)(P + (size_t)r1 * OUTF + f) = make_float2(acc[mt][nt][0], acc[mt][nt][1]);
            *(float2*)(P + (size_t)(r1 + 8) * OUTF + f) = make_float2(acc[mt][nt][2], acc[mt][nt][3]);
        }
    }
#undef CPST
}

// ---------------- launch 4: reduce partials + permute + unscale ----------------
__global__ void k_red(float* __restrict__ out) {
    const float dsc = 1.f / 1024.f;
    int idx = blockIdx.x * 256 + threadIdx.x;     // 524288
    int r = idx >> 5, f4 = (idx & 31) * 4;
    float4 a = *(const float4*)(g_Pk + (size_t)r * OUTF + f4);
    float4 b = *(const float4*)(g_Pk + 2097152 + (size_t)r * OUTF + f4);
    int n = r & (Nn - 1), c = r >> 12;
    *(float4*)(out + (size_t)n * 512 + c * OUTF + f4) =
        make_float4((a.x + b.x) * dsc, (a.y + b.y) * dsc,
                    (a.z + b.z) * dsc, (a.w + b.w) * dsc);
}

// ---------------- launch ----------------
extern "C" void kernel_launch(void* const* d_in, const int* in_sizes, int n_in,
                              void* d_out, int out_size) {
    const float* x = (const float*)d_in[0];
    const float* att = (const float*)d_in[1];
    const float* W = (const float*)d_in[2];
    const unsigned char* mask = (const unsigned char*)d_in[3];
    float* out = (float*)d_out;

    static const int SMEM2 = 98304;   // 3 stages x 32KB
    cudaFuncSetAttribute(k_gemm2m, cudaFuncAttributeMaxDynamicSharedMemorySize, SMEM2);

    k_meanpart<<<1024, 256>>>((const float4*)att, W, mask);   // 0: mean + Wt + detect
    k_fused1<<<1152, 256>>>(x, att, mask);                    // 1: gemm1 + colsum/Af
    k_bprep<<<dim3(128, 4), 256>>>();                         // 2
    k_gemm2m<<<dim3(128, 2), 256, SMEM2>>>();                 // 3  <- expect ncu capture here
    k_red<<<2048, 256>>>(out);                                // 4
}